// round 6
// baseline (speedup 1.0000x reference)
#include <cuda_runtime.h>
#include <stdint.h>

// B=256 graphs, M=512 atoms, K=33 neighbors (incl self), radius 5.0
// Output float32 concatenated: src[E], dst[E], dist[E], mask[E], E = B*M*K
#define BGRAPH 256
#define MPTS   512
#define KNN    33
#define QPB    256                       // queries per CTA (2 CTAs per graph)
#define NCTA   ((BGRAPH * MPTS) / QPB)   // 512
#define CAP    42                        // collect buffer capacity per query
#define NBINS  64
#define RADIUS 5.0f

typedef unsigned long long ull;

// Shared layout (per CTA):
//   tile : float4[512]                      8192 B
//   bufD : u32 [CAP+1][QPB+1] (padded)     44204 B   (64-bin histogram overlays bufD+bufI;
//   bufI : u16 [CAP+1][QPB+2] (padded)     22188 B    phases separated by __syncthreads)
// total 74584 B -> 3 CTAs/SM
#define BUFD_STRIDE (QPB + 1)            // words; +1 pad -> conflict-free column access
#define BUFI_STRIDE (QPB + 2)            // halves
#define TILE_BYTES  (MPTS * 16)
#define BUFD_BYTES  ((CAP + 1) * BUFD_STRIDE * 4)
#define BUFI_BYTES  ((CAP + 1) * BUFI_STRIDE * 2)
#define SMEM_BYTES  (TILE_BYTES + BUFD_BYTES + BUFI_BYTES)
static_assert(NBINS * QPB * 4 <= BUFD_BYTES + BUFI_BYTES, "hist overlay must fit");

// Composite 48-bit key: (d2_bits << 16) | idx  -> exact (d2, idx) lexicographic order,
// matching lax.top_k stability (ascending d2, lower index first on ties).
__device__ __forceinline__ ull ldk(const uint32_t* bD, const uint16_t* bI, int i) {
    return ((ull)bD[i * BUFD_STRIDE] << 16) | bI[i * BUFI_STRIDE];
}
__device__ __forceinline__ void stk(uint32_t* bD, uint16_t* bI, int i, ull k) {
    bD[i * BUFD_STRIDE] = (uint32_t)(k >> 16);
    bI[i * BUFI_STRIDE] = (uint16_t)k;
}

__device__ __forceinline__ void sift_down(uint32_t* bD, uint16_t* bI, int start, int nn, ull val) {
    int p = start;
    for (;;) {
        int l = 2 * p + 1;
        if (l >= nn) break;
        ull c = ldk(bD, bI, l);
        int ci = l;
        if (l + 1 < nn) {
            ull cr = ldk(bD, bI, l + 1);
            if (cr > c) { c = cr; ci = l + 1; }
        }
        if (c <= val) break;
        stk(bD, bI, p, c);
        p = ci;
    }
    stk(bD, bI, p, val);
}

extern "C" __global__ void __launch_bounds__(QPB, 3)
knn_graph_kernel(const float* __restrict__ pos, float* __restrict__ out)
{
    extern __shared__ unsigned char smem[];
    float4*   tile = (float4*)smem;
    uint32_t* bufD = (uint32_t*)(smem + TILE_BYTES);
    uint16_t* bufI = (uint16_t*)(smem + TILE_BYTES + BUFD_BYTES);
    uint32_t* hist = (uint32_t*)(smem + TILE_BYTES);   // overlays bufD+bufI (dead after barrier)

    const int cta  = blockIdx.x;
    const int g    = cta >> 1;
    const int qoff = (cta & 1) * QPB;
    const int base = g * MPTS;
    const int tid  = threadIdx.x;

    // ---- Stage positions: coalesced load, pack float4(x,y,z,|p|^2) ----
    {
        float* raw = (float*)(smem + TILE_BYTES);      // scratch in bufD region
        const float* gp = pos + (size_t)base * 3;
        for (int i = tid; i < MPTS * 3; i += QPB) raw[i] = gp[i];
        __syncthreads();
        for (int i = tid; i < MPTS; i += QPB) {
            float x = raw[i * 3 + 0], y = raw[i * 3 + 1], z = raw[i * 3 + 2];
            tile[i] = make_float4(x, y, z, x * x + y * y + z * z);
        }
        __syncthreads();
    }

    const int q = qoff + tid;                          // this thread's query (0..511 in graph)
    const float4 me = tile[q];
    const float px = me.x, py = me.y, pz = me.z, sq = me.w;

    // ---- Threshold selection: per-thread private 64-bin histograms on d2 bits ----
    // Pass 0 window is placed by a local-density model (Gaussian cloud, sigma=8):
    // T33(q) ~= 25*exp(|q|^2/192). Float bits are log-space, so est_bits is LINEAR in sq:
    //   est = bits(25.0) + sq * 2^23/(192*ln2) = 0x41C80000 + sq*63032.
    // 64 bins of 1/16 octave (sh=19), estimate at bin 56: covers overestimation (outlier
    // queries, where the model overshoots) down to x11, undershoot up to x1.4.
    // Correctness NEVER depends on the estimate: exact-count invariants below.
    //   - low-clamp bin 0 keeps cumulative counts EXACT (everything in it is below its edge)
    //   - high-clamp bin 63 inflates nT -> only trust/break on bstar < 63
    //   - any failure -> reset to the proven full-range octave scheme (fb path)
    uint32_t* histq = hist + tid;
    uint32_t est = 0x41C80000u + (uint32_t)(int)(sq * 63032.0f);
    uint32_t lo  = est - (56u << 19);
    int      sh  = 19;
    uint32_t Tsel = 0xFFFFFFFFu;
    bool     fb   = false;

    for (int pass = 0; pass < 8; ++pass) {
        #pragma unroll
        for (int b = 0; b < NBINS; ++b) histq[b << 8] = 0u;

        #pragma unroll 8
        for (int c = 0; c < MPTS; ++c) {
            float4 t = tile[c];
            float dot = px * t.x + py * t.y + pz * t.z;
            float d2  = fmaf(-2.0f, dot, sq + t.w);    // negative bits -> signed shift -> bin 0: exact
            uint32_t key = __float_as_uint(d2);
            int bin = (int)(key - lo) >> sh;           // arithmetic shift; clamp under/overflow
            bin = bin < 0 ? 0 : (bin > NBINS - 1 ? NBINS - 1 : bin);
            histq[bin << 8] += 1u;
        }

        uint32_t cum = 0, nT = 0;
        int bstar = -1;
        #pragma unroll
        for (int b = 0; b < NBINS; ++b) {
            cum += histq[b << 8];
            if (bstar < 0 && cum >= KNN) { bstar = b; nT = cum; }
        }

        if (bstar < NBINS - 1) {
            Tsel = lo + ((uint32_t)(bstar + 1) << sh); // exact: nT keys strictly below Tsel
            if (nT <= CAP) break;
        }
        if (!fb) {                                     // estimator failed -> proven full-range scheme
            fb = true;
            lo = 120u << 23;                           // octave bins from d2=2^-7; 64 octaves = all floats
            sh = 23;
        } else {                                       // refine into boundary bin (tiles it exactly)
            lo += (uint32_t)bstar << sh;
            sh  = sh > 6 ? sh - 6 : 0;
        }
    }

    // hist overlays bufD/bufI and warps exit the pass loop after different pass counts;
    // without this barrier early warps' collect writes race late warps' live histograms.
    __syncthreads();

    // ---- Branch-free collect: all candidates with key < Tsel ----
    uint32_t* bDq = bufD + tid;
    uint16_t* bIq = bufI + tid;
    uint32_t cnt = 0;
    #pragma unroll 8
    for (int c = 0; c < MPTS; ++c) {
        float4 t = tile[c];
        float dot = px * t.x + py * t.y + pz * t.z;
        float d2  = fmaxf(fmaf(-2.0f, dot, sq + t.w), 0.0f);  // normalize -eps -> +0 for stored keys
        uint32_t key = __float_as_uint(d2);
        uint32_t slot = cnt < CAP ? cnt : CAP;         // row CAP = scratch (absorbs non-passing writes)
        bDq[slot * BUFD_STRIDE] = key;                 // unconditional store; a passing candidate
        bIq[slot * BUFI_STRIDE] = (uint16_t)c;         // claims the slot by advancing cnt
        cnt += (key < Tsel) ? 1u : 0u;
    }
    uint32_t n = cnt;
    if (n > CAP) n = CAP;                              // safety rail; slots 0..CAP-1 valid
    if (n < KNN) {                                     // safety rail: pad with +inf keys, valid idx 0
        for (uint32_t i = n; i < KNN; ++i) stk(bDq, bIq, (int)i, ((ull)0xFFFFFFFFu << 16));
        n = KNN;
    }

    // ---- Exact top-33 + ascending sort over <=42 elements (composite key: tie-break by idx) ----
    for (int i = KNN / 2 - 1; i >= 0; --i) {
        ull v = ldk(bDq, bIq, i);
        sift_down(bDq, bIq, i, KNN, v);
    }
    ull root = ldk(bDq, bIq, 0);
    for (uint32_t i = KNN; i < n; ++i) {
        ull v = ldk(bDq, bIq, (int)i);
        if (v < root) { sift_down(bDq, bIq, 0, KNN, v); root = ldk(bDq, bIq, 0); }
    }
    for (int end = KNN - 1; end > 0; --end) {          // heapsort -> ascending (d2, idx) in slots 0..32
        ull maxv = ldk(bDq, bIq, 0);
        ull last = ldk(bDq, bIq, end);
        stk(bDq, bIq, end, maxv);
        sift_down(bDq, bIq, 0, end, last);
    }
    __syncwarp();                                      // output reads same-warp lanes' columns only

    // ---- Coalesced output: warp covers its 32 queries' 32*33 edges linearly ----
    const int warp = tid >> 5;
    const int lane = tid & 31;
    const int q0   = warp << 5;                        // within CTA
    const long E   = (long)BGRAPH * MPTS * KNN;        // 4,325,376
    const long eBase = (long)(base + qoff + q0) * KNN;

    for (int j = lane; j < 32 * KNN; j += 32) {
        int qi = j / KNN;
        int k  = j - qi * KNN;
        int qlocal = q0 + qi;
        int c  = (int)bufI[k * BUFI_STRIDE + qlocal];
        int qq = qoff + qlocal;

        float4 a = tile[c];                            // src = neighbor
        float4 b = tile[qq];                           // dst = center
        float dx = a.x - b.x, dy = a.y - b.y, dz = a.z - b.z;
        float dd = dx * dx + dy * dy + dz * dz;        // reference recomputes from gathered endpoints
        float dist = (dd > 0.0f) ? sqrtf(dd) : 0.0f;

        long e = eBase + j;
        out[e]         = (float)(base + c);
        out[E + e]     = (float)(base + qq);
        out[2 * E + e] = dist;
        out[3 * E + e] = (dist <= RADIUS) ? 1.0f : 0.0f;
    }
}

extern "C" void kernel_launch(void* const* d_in, const int* in_sizes, int n_in,
                              void* d_out, int out_size) {
    const float* pos = (const float*)d_in[0];          // [B*M, 3] float32 (batch input unused: uniform)
    float* out = (float*)d_out;
    cudaFuncSetAttribute(knn_graph_kernel,
                         cudaFuncAttributeMaxDynamicSharedMemorySize, (int)SMEM_BYTES);
    knn_graph_kernel<<<NCTA, QPB, SMEM_BYTES>>>(pos, out);
}

// round 8
// speedup vs baseline: 1.8314x; 1.8314x over previous
#include <cuda_runtime.h>
#include <stdint.h>

// B=256 graphs, M=512 atoms, K=33 neighbors (incl self), radius 5.0
// Output float32 concatenated: src[E], dst[E], dist[E], mask[E], E = B*M*K
#define BGRAPH 256
#define MPTS   512
#define KNN    33
#define QPB    256                       // queries per CTA (2 CTAs per graph)
#define NCTA   ((BGRAPH * MPTS) / QPB)   // 512
#define CAP    42                        // collect buffer capacity per query (also sizes hist overlay)
#define RADIUS 5.0f

typedef unsigned long long ull;

// Shared layout (per CTA):
//   tile : float4[512]                      8192 B
//   bufD : u32 [CAP+1][QPB+1] (padded)     44204 B   (histograms overlay bufD+bufI;
//   bufI : u16 [CAP+1][QPB+2] (padded)     22188 B    phases separated by __syncthreads)
// total 74584 B -> 3 CTAs/SM (same footprint as the round-6 kernel, which launched fine)
#define BUFD_STRIDE (QPB + 1)            // words; +1 pad -> conflict-free column access
#define BUFI_STRIDE (QPB + 2)            // halves
#define TILE_BYTES  (MPTS * 16)
#define BUFD_BYTES  ((CAP + 1) * BUFD_STRIDE * 4)
#define BUFI_BYTES  ((CAP + 1) * BUFI_STRIDE * 2)
#define SMEM_BYTES  (TILE_BYTES + BUFD_BYTES + BUFI_BYTES)
// Hist overlay: histA[32][256] + histB[32][256] u32 words, each packing two u16 counters.
static_assert(64 * QPB * 4 <= BUFD_BYTES + BUFI_BYTES, "hist overlay must fit in buf region");

// Composite 48-bit key: (d2_bits << 16) | idx  -> exact (d2, idx) lexicographic order,
// matching lax.top_k stability (ascending d2, lower index first on ties).
__device__ __forceinline__ ull ldk(const uint32_t* bD, const uint16_t* bI, int i) {
    return ((ull)bD[i * BUFD_STRIDE] << 16) | bI[i * BUFI_STRIDE];
}
__device__ __forceinline__ void stk(uint32_t* bD, uint16_t* bI, int i, ull k) {
    bD[i * BUFD_STRIDE] = (uint32_t)(k >> 16);
    bI[i * BUFI_STRIDE] = (uint16_t)k;
}

__device__ __forceinline__ void sift_down(uint32_t* bD, uint16_t* bI, int start, int nn, ull val) {
    int p = start;
    for (;;) {
        int l = 2 * p + 1;
        if (l >= nn) break;
        ull c = ldk(bD, bI, l);
        int ci = l;
        if (l + 1 < nn) {
            ull cr = ldk(bD, bI, l + 1);
            if (cr > c) { c = cr; ci = l + 1; }
        }
        if (c <= val) break;
        stk(bD, bI, p, c);
        p = ci;
    }
    stk(bD, bI, p, val);
}

extern "C" __global__ void __launch_bounds__(QPB, 3)
knn_graph_kernel(const float* __restrict__ pos, float* __restrict__ out)
{
    extern __shared__ unsigned char smem[];
    float4*   tile = (float4*)smem;
    uint32_t* bufD = (uint32_t*)(smem + TILE_BYTES);
    uint16_t* bufI = (uint16_t*)(smem + TILE_BYTES + BUFD_BYTES);
    uint32_t* histA = (uint32_t*)(smem + TILE_BYTES);          // overlays buf region (dead
    uint32_t* histB = histA + 32 * QPB;                        //  after the barrier below)

    const int cta  = blockIdx.x;
    const int g    = cta >> 1;
    const int qoff = (cta & 1) * QPB;
    const int base = g * MPTS;
    const int tid  = threadIdx.x;

    // ---- Stage positions: coalesced load, pack float4(x,y,z,|p|^2) ----
    {
        float* raw = (float*)(smem + TILE_BYTES);      // scratch in buf region
        const float* gp = pos + (size_t)base * 3;
        for (int i = tid; i < MPTS * 3; i += QPB) raw[i] = gp[i];
        __syncthreads();
        for (int i = tid; i < MPTS; i += QPB) {
            float x = raw[i * 3 + 0], y = raw[i * 3 + 1], z = raw[i * 3 + 2];
            tile[i] = make_float4(x, y, z, x * x + y * y + z * z);
        }
        __syncthreads();
    }

    const int q = qoff + tid;                          // this thread's query (0..511 in graph)
    const float4 me = tile[q];
    const float px = me.x, py = me.y, pz = me.z, sq = me.w;

    // ---- Threshold refinement: per-thread 32-bin histograms, 4 independent RMW chains ----
    // The naive hist RMW (LDS->IADD->STS at a dynamic bin) is an alias-serialized ~35cyc
    // chain per candidate. We split candidates round-robin over 4 sub-counters: two u32
    // arrays (A,B), each word packing two u16 counts (lo=+1, hi=+0x10000). A/B chains are
    // independent -> MLP>=2; within-array collisions stay correct (ordered RMW). Each
    // sub-hist sees 128 candidates, so halves never overflow or carry into each other.
    // Octave bins pass 1 (exact full coverage), 1/32-octave refine pass 2:
    //   - low-clamp bin 0 keeps cumulative counts EXACT
    //   - high-clamp bin 31 inflates nT -> only trust/break on bstar < 31; refine anyway
    uint32_t* hAq = histA + tid;                       // hAq[b<<8], conflict-free columns
    uint32_t* hBq = histB + tid;
    uint32_t lo = 120u << 23;                          // octave bins: d2 in [2^-7, 2^24)
    int      sh = 23;
    uint32_t Tsel = 0xFFFFFFFFu;

    for (int pass = 0; pass < 10; ++pass) {
        #pragma unroll
        for (int b = 0; b < 32; ++b) { hAq[b << 8] = 0u; hBq[b << 8] = 0u; }

        #pragma unroll 2
        for (int c = 0; c < MPTS; c += 4) {
            float4 t0 = tile[c + 0];
            float4 t1 = tile[c + 1];
            float4 t2 = tile[c + 2];
            float4 t3 = tile[c + 3];
            float d0 = fmaf(-2.0f, px * t0.x + py * t0.y + pz * t0.z, sq + t0.w);
            float d1 = fmaf(-2.0f, px * t1.x + py * t1.y + pz * t1.z, sq + t1.w);
            float d2 = fmaf(-2.0f, px * t2.x + py * t2.y + pz * t2.z, sq + t2.w);
            float d3 = fmaf(-2.0f, px * t3.x + py * t3.y + pz * t3.z, sq + t3.w);
            // negative-ulp d2 bits -> negative signed diff -> clamped to bin 0: exact
            int b0 = (int)(__float_as_uint(d0) - lo) >> sh;
            int b1 = (int)(__float_as_uint(d1) - lo) >> sh;
            int b2 = (int)(__float_as_uint(d2) - lo) >> sh;
            int b3 = (int)(__float_as_uint(d3) - lo) >> sh;
            b0 = b0 < 0 ? 0 : (b0 > 31 ? 31 : b0);
            b1 = b1 < 0 ? 0 : (b1 > 31 ? 31 : b1);
            b2 = b2 < 0 ? 0 : (b2 > 31 ? 31 : b2);
            b3 = b3 < 0 ? 0 : (b3 > 31 ? 31 : b3);
            hAq[b0 << 8] += 1u;
            hAq[b1 << 8] += 0x10000u;
            hBq[b2 << 8] += 1u;
            hBq[b3 << 8] += 0x10000u;
        }

        uint32_t cumP = 0, nT = 0;                     // packed cumulative (lo/hi halves)
        int bstar = -1;
        #pragma unroll
        for (int b = 0; b < 32; ++b) {
            cumP += hAq[b << 8] + hBq[b << 8];
            uint32_t tot = (cumP & 0xFFFFu) + (cumP >> 16);
            if (bstar < 0 && tot >= KNN) { bstar = b; nT = tot; }
        }

        if (bstar < 31) {
            Tsel = lo + ((uint32_t)(bstar + 1) << sh); // exact: nT keys strictly below Tsel
            if (nT <= CAP) break;
        }
        // refine into boundary bin (uniform for bstar==31: tiles the old bin exactly)
        lo += (uint32_t)bstar << sh;
        sh  = sh > 5 ? sh - 5 : 0;
    }

    // hist overlays bufD/bufI and warps exit the pass loop after different pass counts;
    // without this barrier early warps' collect writes race late warps' live histograms.
    __syncthreads();

    // ---- Branch-free collect: all candidates with key < Tsel ----
    uint32_t* bDq = bufD + tid;
    uint16_t* bIq = bufI + tid;
    uint32_t cnt = 0;
    #pragma unroll 8
    for (int c = 0; c < MPTS; ++c) {
        float4 t = tile[c];
        float dot = px * t.x + py * t.y + pz * t.z;
        float d2  = fmaxf(fmaf(-2.0f, dot, sq + t.w), 0.0f);  // normalize -eps -> +0 for stored keys
        uint32_t key = __float_as_uint(d2);
        uint32_t slot = cnt < CAP ? cnt : CAP;         // row CAP = scratch (absorbs non-passing writes)
        bDq[slot * BUFD_STRIDE] = key;                 // unconditional store; a passing candidate
        bIq[slot * BUFI_STRIDE] = (uint16_t)c;         // claims the slot by advancing cnt
        cnt += (key < Tsel) ? 1u : 0u;
    }
    uint32_t n = cnt;
    if (n > CAP) n = CAP;                              // safety rail; slots 0..CAP-1 valid
    if (n < KNN) {                                     // safety rail: pad with +inf keys, valid idx 0
        for (uint32_t i = n; i < KNN; ++i) stk(bDq, bIq, (int)i, ((ull)0xFFFFFFFFu << 16));
        n = KNN;
    }

    // ---- Exact top-33 + ascending sort over <=42 elements (composite key: tie-break by idx) ----
    for (int i = KNN / 2 - 1; i >= 0; --i) {
        ull v = ldk(bDq, bIq, i);
        sift_down(bDq, bIq, i, KNN, v);
    }
    ull root = ldk(bDq, bIq, 0);
    for (uint32_t i = KNN; i < n; ++i) {
        ull v = ldk(bDq, bIq, (int)i);
        if (v < root) { sift_down(bDq, bIq, 0, KNN, v); root = ldk(bDq, bIq, 0); }
    }
    for (int end = KNN - 1; end > 0; --end) {          // heapsort -> ascending (d2, idx) in slots 0..32
        ull maxv = ldk(bDq, bIq, 0);
        ull last = ldk(bDq, bIq, end);
        stk(bDq, bIq, end, maxv);
        sift_down(bDq, bIq, 0, end, last);
    }
    __syncwarp();                                      // output reads same-warp lanes' columns only

    // ---- Coalesced output: warp covers its 32 queries' 32*33 edges linearly ----
    const int warp = tid >> 5;
    const int lane = tid & 31;
    const int q0   = warp << 5;                        // within CTA
    const long E   = (long)BGRAPH * MPTS * KNN;        // 4,325,376
    const long eBase = (long)(base + qoff + q0) * KNN;

    for (int j = lane; j < 32 * KNN; j += 32) {
        int qi = j / KNN;
        int k  = j - qi * KNN;
        int qlocal = q0 + qi;
        int c  = (int)bufI[k * BUFI_STRIDE + qlocal];
        int qq = qoff + qlocal;

        float4 a = tile[c];                            // src = neighbor
        float4 b = tile[qq];                           // dst = center
        float dx = a.x - b.x, dy = a.y - b.y, dz = a.z - b.z;
        float dd = dx * dx + dy * dy + dz * dz;        // reference recomputes from gathered endpoints
        float dist = (dd > 0.0f) ? sqrtf(dd) : 0.0f;

        long e = eBase + j;
        out[e]         = (float)(base + c);
        out[E + e]     = (float)(base + qq);
        out[2 * E + e] = dist;
        out[3 * E + e] = (dist <= RADIUS) ? 1.0f : 0.0f;
    }
}

extern "C" void kernel_launch(void* const* d_in, const int* in_sizes, int n_in,
                              void* d_out, int out_size) {
    const float* pos = (const float*)d_in[0];          // [B*M, 3] float32 (batch input unused: uniform)
    float* out = (float*)d_out;
    cudaFuncSetAttribute(knn_graph_kernel,
                         cudaFuncAttributeMaxDynamicSharedMemorySize, (int)SMEM_BYTES);
    knn_graph_kernel<<<NCTA, QPB, SMEM_BYTES>>>(pos, out);
}